// round 3
// baseline (speedup 1.0000x reference)
#include <cuda_runtime.h>
#include <cstdint>

// DisulfideEnergy: sulfur-pair energy scatter + residue segment reduction.
//
// Inputs (metadata order):
//   d_in[0] coords            f32  [500000, 3]
//   d_in[1] atom_description  i32  [500000, 4]  (at_name, resnum, batch, chain)
//   d_in[2] atom_pairs        i32  [4000000, 2]
//   d_in[3] alternative_mask  [500000, 4] — bool converted to a 4-byte dtype
//                             (f32 or i32); read as u32, nonzero == true
//   d_in[4] facc              f32  [500000]     (UNUSED by reference)
// Output (single f32 buffer, concatenated flatten order):
//   [0 .. 64000)              resi_energy (8,4,500,4)
//   [64000 .. 2064000)        atom_energy (500000,4)
//   [2064000 .. 6064000)      sulfur      (4000000) as 0.0/1.0

#define N_CHAINS   4
#define N_RES      500
#define SG_CODE    7
#define MAX_ATOMS  500000
#define MAX_WORDS  ((MAX_ATOMS + 31) / 32)   // 15625

__device__ uint32_t g_sgmask[MAX_WORDS + 32];

// ---------------------------------------------------------------------------
// Kernel 1: build SG bitmask, zero resi + atom_energy regions of d_out.
// ---------------------------------------------------------------------------
__global__ void init_kernel(const int* __restrict__ desc,
                            float* __restrict__ out,
                            int n_atoms, int resi_floats)
{
    int t = blockIdx.x * blockDim.x + threadIdx.x;

    int an = (t < n_atoms) ? desc[4 * t] : 0;          // at_name column
    unsigned ball = __ballot_sync(0xffffffffu, an == SG_CODE);
    if ((threadIdx.x & 31) == 0 && t < n_atoms)
        g_sgmask[t >> 5] = ball;

    if (t < resi_floats)                               // zero resi region
        out[t] = 0.0f;

    if (t < n_atoms) {                                 // zero atom_energy region
        float4 z = make_float4(0.f, 0.f, 0.f, 0.f);
        reinterpret_cast<float4*>(out + resi_floats)[t] = z;
    }
}

// ---------------------------------------------------------------------------
// Heavy path: only executed for true sulfur pairs (~1/1600 of pairs).
// amask is u32 per (atom, alt): nonzero == true (covers f32 1.0 and i32 1).
// ---------------------------------------------------------------------------
__device__ __forceinline__ void heavy_pair(int i, int j,
                                           const float* __restrict__ coords,
                                           const int* __restrict__ desc,
                                           const uint32_t* __restrict__ amask,
                                           float* __restrict__ atomE)
{
    float dx = __ldg(coords + 3 * i + 0) - __ldg(coords + 3 * j + 0) + 1e-6f;
    float dy = __ldg(coords + 3 * i + 1) - __ldg(coords + 3 * j + 1) + 1e-6f;
    float dz = __ldg(coords + 3 * i + 2) - __ldg(coords + 3 * j + 2) + 1e-6f;
    float dist = sqrtf(dx * dx + dy * dy + dz * dz);

    int ri = __ldg(desc + 4 * i + 1);
    int rj = __ldg(desc + 4 * j + 1);
    float rd  = fabsf((float)(ri - rj));
    float rds = (rd > 0.f) ? rd : 1.0f;

    // -0.001*298.0 = -0.298
    float energy = -0.298f * (2.1f + 2.9823825f * logf(rds))
                 + 5.0f * fabsf(dist - 2.04f);
    float net = 0.5f * energy;

    uint4 mi = *reinterpret_cast<const uint4*>(amask + 4 * (size_t)i);
    uint4 mj = *reinterpret_cast<const uint4*>(amask + 4 * (size_t)j);

    if (mi.x && mj.x) { atomicAdd(atomE + 4*(size_t)i + 0, net);
                        atomicAdd(atomE + 4*(size_t)j + 0, net); }
    if (mi.y && mj.y) { atomicAdd(atomE + 4*(size_t)i + 1, net);
                        atomicAdd(atomE + 4*(size_t)j + 1, net); }
    if (mi.z && mj.z) { atomicAdd(atomE + 4*(size_t)i + 2, net);
                        atomicAdd(atomE + 4*(size_t)j + 2, net); }
    if (mi.w && mj.w) { atomicAdd(atomE + 4*(size_t)i + 3, net);
                        atomicAdd(atomE + 4*(size_t)j + 3, net); }
}

// ---------------------------------------------------------------------------
// Kernel 2: pair sweep. SG bitmask staged in shared memory (62.5 KB),
// 2 pairs per thread-iteration (int4 load, float2 store).
// ---------------------------------------------------------------------------
__global__ void pair_kernel(const int4* __restrict__ pairs2,
                            const float* __restrict__ coords,
                            const int* __restrict__ desc,
                            const uint32_t* __restrict__ amask,
                            float* __restrict__ out,
                            int n_pairs, int n_atoms, int resi_floats)
{
    extern __shared__ uint32_t smask[];
    int nwords = (n_atoms + 31) >> 5;
    for (int w = threadIdx.x; w < nwords; w += blockDim.x)
        smask[w] = g_sgmask[w];
    __syncthreads();

    float* atomE = out + resi_floats;
    float* sout  = atomE + 4 * (size_t)n_atoms;

    int n2 = n_pairs >> 1;
    int stride = gridDim.x * blockDim.x;

    for (int p = blockIdx.x * blockDim.x + threadIdx.x; p < n2; p += stride) {
        int4 pr = pairs2[p];

        unsigned s0 = (smask[pr.x >> 5] >> (pr.x & 31))
                    & (smask[pr.y >> 5] >> (pr.y & 31)) & 1u;
        unsigned s1 = (smask[pr.z >> 5] >> (pr.z & 31))
                    & (smask[pr.w >> 5] >> (pr.w & 31)) & 1u;

        float2 so;
        so.x = s0 ? 1.0f : 0.0f;
        so.y = s1 ? 1.0f : 0.0f;
        reinterpret_cast<float2*>(sout)[p] = so;

        if (s0) heavy_pair(pr.x, pr.y, coords, desc, amask, atomE);
        if (s1) heavy_pair(pr.z, pr.w, coords, desc, amask, atomE);
    }

    // odd tail (n_pairs is even for this problem, but stay general)
    if ((n_pairs & 1) && blockIdx.x == 0 && threadIdx.x == 0) {
        const int* pp = reinterpret_cast<const int*>(pairs2);
        int i = pp[2 * (n_pairs - 1)];
        int j = pp[2 * (n_pairs - 1) + 1];
        unsigned s = (smask[i >> 5] >> (i & 31)) & (smask[j >> 5] >> (j & 31)) & 1u;
        sout[n_pairs - 1] = s ? 1.0f : 0.0f;
        if (s) heavy_pair(i, j, coords, desc, amask, atomE);
    }
}

// ---------------------------------------------------------------------------
// Kernel 3: residue segment-sum. Skip all-zero atoms (vast majority).
// ---------------------------------------------------------------------------
__global__ void resi_kernel(const int4* __restrict__ desc4,
                            float* __restrict__ out,
                            int n_atoms, int resi_floats)
{
    int t = blockIdx.x * blockDim.x + threadIdx.x;
    if (t >= n_atoms) return;

    float4 e = reinterpret_cast<const float4*>(out + resi_floats)[t];
    if ((e.x != 0.f) | (e.y != 0.f) | (e.z != 0.f) | (e.w != 0.f)) {
        int4 d = desc4[t];   // (at_name, resnum, batch, chain)
        int flat = (d.z * N_CHAINS + d.w) * N_RES + d.y;
        float* r = out + 4 * (size_t)flat;
        if (e.x != 0.f) atomicAdd(r + 0, e.x);
        if (e.y != 0.f) atomicAdd(r + 1, e.y);
        if (e.z != 0.f) atomicAdd(r + 2, e.z);
        if (e.w != 0.f) atomicAdd(r + 3, e.w);
    }
}

// ---------------------------------------------------------------------------
extern "C" void kernel_launch(void* const* d_in, const int* in_sizes, int n_in,
                              void* d_out, int out_size)
{
    const float*    coords = (const float*)d_in[0];
    const int*      desc   = (const int*)d_in[1];
    const int*      pairs  = (const int*)d_in[2];
    const uint32_t* amask  = (const uint32_t*)d_in[3];
    float*          out    = (float*)d_out;

    int n_atoms = in_sizes[0] / 3;
    int n_pairs = in_sizes[2] / 2;
    int n_alt   = in_sizes[3] / n_atoms;            // 4
    // resi region size = out_size - atom_energy - sulfur
    int resi_floats = out_size - n_atoms * n_alt - n_pairs;   // 64000

    int nwords = (n_atoms + 31) >> 5;
    size_t smem = (size_t)nwords * 4;               // 62500 B

    cudaFuncSetAttribute(pair_kernel,
                         cudaFuncAttributeMaxDynamicSharedMemorySize,
                         (int)smem);

    int threads = 256;
    int ablocks = (n_atoms + threads - 1) / threads;

    init_kernel<<<ablocks, threads>>>(desc, out, n_atoms, resi_floats);

    // 3 CTAs/SM (smem-limited: 3 * 62.5KB < 228KB), 148 SMs
    pair_kernel<<<444, 512, smem>>>((const int4*)pairs, coords, desc, amask,
                                    out, n_pairs, n_atoms, resi_floats);

    resi_kernel<<<ablocks, threads>>>((const int4*)desc, out,
                                      n_atoms, resi_floats);
}